// round 16
// baseline (speedup 1.0000x reference)
#include <cuda_runtime.h>
#include <cuda_fp16.h>
#include <cstdint>

typedef unsigned long long u64;
typedef unsigned int u32;

#define BATCH   4096
#define DIN     512
#define NTREES  64
#define NCOLSV  4032        // valid gate columns
#define GCOLS   4096        // padded gate columns
#define KLT     4096
#define LDIM    128
#define SPLITK2 4

// ---------------- scratch (device globals: allocation-free) ----------------
__device__ __half g_buf[(size_t)BATCH * GCOLS];     // sigmoid gates [b][col] fp16
__device__ __half xh_buf[(size_t)BATCH * DIN];      // x fp16
__device__ __half wth_buf[(size_t)GCOLS * DIN];     // W transposed [col][k] fp16
__device__ __half ph_buf[(size_t)BATCH * KLT];      // leaf probs fp16
__device__ __half w2th_buf[(size_t)LDIM * KLT];     // leaf_w*softmax transposed fp16
__device__ float  part_buf[SPLITK2 * (size_t)BATCH * LDIM];

// ---------------- helpers ----------------
__device__ __forceinline__ u32 smem_u32(const void* p) {
    u32 a;
    asm("{ .reg .u64 t; cvta.to.shared.u64 t, %1; cvt.u32.u64 %0, t; }" : "=r"(a) : "l"(p));
    return a;
}
// fast sigmoid: guaranteed MUFU path independent of compile flags
__device__ __forceinline__ float sigf(float z) {
    return __fdividef(1.0f, 1.0f + __expf(-z));
}

#define LDSM_X4(r0, r1, r2, r3, addr) \
    asm volatile("ldmatrix.sync.aligned.m8n8.x4.shared.b16 {%0,%1,%2,%3}, [%4];" \
                 : "=r"(r0), "=r"(r1), "=r"(r2), "=r"(r3) : "r"(addr))

#define MMA16816(d, a, b0, b1) \
    asm volatile("mma.sync.aligned.m16n8k16.row.col.f32.f16.f16.f32 " \
                 "{%0,%1,%2,%3}, {%4,%5,%6,%7}, {%8,%9}, {%0,%1,%2,%3};" \
                 : "+f"((d)[0]), "+f"((d)[1]), "+f"((d)[2]), "+f"((d)[3]) \
                 : "r"((a)[0]), "r"((a)[1]), "r"((a)[2]), "r"((a)[3]), \
                   "r"(b0), "r"(b1))

#define CPA(dst, src) \
    asm volatile("cp.async.cg.shared.global [%0], [%1], 16;" :: "r"(dst), "l"(src))
#define CP_COMMIT() asm volatile("cp.async.commit_group;" ::: "memory")
#define CP_WAIT3()  asm volatile("cp.async.wait_group 3;" ::: "memory")

// ============================================================================
// GEMM1: g = sigmoid(x @ wt^T + bias) -> fp16.  grid (32, 16) per half.
// C[128,128] CTA tile, 8 warps of 64x32, K-chunks of 32, 5-stage cp.async.
// Swizzle: 16B chunk c' = c ^ ((row>>1)&3); row stride 64B.   (R12 config)
// ============================================================================
#define KC 32
#define NSTAGE 5
#define T_BH   8192u
#define STG_B  16384u
#define OFF_BIAS (NSTAGE * STG_B)
#define SMEM_G1 (OFF_BIAS + 512)

__global__ __launch_bounds__(256, 2)
void hmma1_kernel(const float* __restrict__ bias, int bm_off) {
    extern __shared__ char smem[];
    const u32 sb = smem_u32(smem);
    const int tid  = threadIdx.x;
    const int wid  = tid >> 5;
    const int lane = tid & 31;

    const int bn = blockIdx.x * 128;
    const int bm = (blockIdx.y + bm_off) * 128;

    if (tid < 128) {
        int col = bn + tid;
        ((float*)(smem + OFF_BIAS))[tid] = (col < NCOLSV) ? bias[col] : 0.0f;
    }

    const int r0 = tid >> 2;
    const int cc = tid & 3;
    const u32 so = (u32)(r0 * 64 + ((cc ^ ((r0 >> 1) & 3)) << 4));

    const __half* gA0 = xh_buf + (size_t)(bm + r0) * DIN + cc * 8;
    const __half* gA1 = gA0 + 64 * DIN;
    const __half* gB0 = wth_buf + (size_t)(bn + r0) * DIN + cc * 8;
    const __half* gB1 = gB0 + 64 * DIN;

    const int mw = (wid & 1) * 64;
    const int nw = (wid >> 1) * 32;
    const int rowA_l = mw + (lane & 15);
    const int rowB_l = (lane & 7) | ((lane >> 1) & 8);
    u32 aoff[2], boff[2];
    #pragma unroll
    for (int kk = 0; kk < 2; kk++) {
        int chA = kk * 2 + (lane >> 4);
        int chB = kk * 2 + ((lane >> 3) & 1);
        aoff[kk] = (u32)(rowA_l * 64 + ((chA ^ ((rowA_l >> 1) & 3)) << 4));
        boff[kk] = (u32)(rowB_l * 64 + ((chB ^ ((rowB_l >> 1) & 3)) << 4)) + (u32)(nw * 64);
    }

    float acc[4][4][4];
    #pragma unroll
    for (int i = 0; i < 4; i++)
        #pragma unroll
        for (int j = 0; j < 4; j++)
            #pragma unroll
            for (int e = 0; e < 4; e++) acc[i][j][e] = 0.0f;

    const int NCH = 16;

    #pragma unroll
    for (int c0 = 0; c0 < NSTAGE - 1; c0++) {
        const u32 base = sb + c0 * STG_B;
        const int o = c0 * KC;
        CPA(base + so,        gA0 + o);
        CPA(base + so + 4096, gA1 + o);
        CPA(base + T_BH + so,        gB0 + o);
        CPA(base + T_BH + so + 4096, gB1 + o);
        CP_COMMIT();
    }

    int sc = NSTAGE - 1;
    for (int c = 0; c < NCH; c++) {
        CP_WAIT3();
        __syncthreads();

        if (c + NSTAGE - 1 < NCH) {
            const u32 base = sb + sc * STG_B;
            const int o = (c + NSTAGE - 1) * KC;
            CPA(base + so,        gA0 + o);
            CPA(base + so + 4096, gA1 + o);
            CPA(base + T_BH + so,        gB0 + o);
            CPA(base + T_BH + so + 4096, gB1 + o);
        }
        CP_COMMIT();
        sc = (sc == NSTAGE - 1) ? 0 : sc + 1;

        const u32 tb = sb + (u32)(c % NSTAGE) * STG_B;
        #pragma unroll
        for (int kk = 0; kk < 2; kk++) {
            u32 Af[4][4], Bv[8];
            #pragma unroll
            for (int f = 0; f < 4; f++)
                LDSM_X4(Af[f][0], Af[f][1], Af[f][2], Af[f][3],
                        tb + aoff[kk] + (u32)(f * 1024));
            #pragma unroll
            for (int gi = 0; gi < 2; gi++)
                LDSM_X4(Bv[4 * gi], Bv[4 * gi + 1], Bv[4 * gi + 2], Bv[4 * gi + 3],
                        tb + T_BH + boff[kk] + (u32)(gi * 1024));
            #pragma unroll
            for (int f = 0; f < 4; f++)
                #pragma unroll
                for (int n = 0; n < 4; n++)
                    MMA16816(acc[f][n], Af[f], Bv[2 * n], Bv[2 * n + 1]);
        }
    }

    const float* bias_s = (const float*)(smem + OFF_BIAS);
    #pragma unroll
    for (int f = 0; f < 4; f++) {
        #pragma unroll
        for (int half = 0; half < 2; half++) {
            const int row_l = mw + f * 16 + (lane >> 2) + half * 8;
            #pragma unroll
            for (int n = 0; n < 4; n++) {
                const int col_l = nw + n * 8 + 2 * (lane & 3);
                float v0 = sigf(acc[f][n][2 * half + 0] + bias_s[col_l]);
                float v1 = sigf(acc[f][n][2 * half + 1] + bias_s[col_l + 1]);
                __half2* o = (__half2*)(g_buf + (size_t)(bm + row_l) * GCOLS + bn + col_l);
                *o = __floats2half2_rn(v0, v1);
            }
        }
    }
}

// ============================================================================
// GEMM2: part[z] = p @ w2t^T (split-K=4).  grid (32 m-tiles, 4 z) per half.
// C[64,128] CTA tile, 8 warps of 32x32, K=1024 per CTA in 32 chunks of 32,
// 5-stage cp.async.  Stage = A(4KB)+B(8KB) = 12KB.   (R12 config)
// ============================================================================
#define NST2  5
#define STG2  12288u
#define SMEM_G2 (NST2 * STG2)

__global__ __launch_bounds__(256, 2)
void hmma2_kernel(int bm_off) {
    extern __shared__ char smem[];
    const u32 sb = smem_u32(smem);
    const int tid  = threadIdx.x;
    const int wid  = tid >> 5;
    const int lane = tid & 31;

    const int bm = (blockIdx.x + bm_off) * 64;
    const int z  = blockIdx.y;
    const long kbase = (long)z * 1024;

    const int r0 = tid >> 2;            // 0..63
    const int cc = tid & 3;
    const u32 so = (u32)(r0 * 64 + ((cc ^ ((r0 >> 1) & 3)) << 4));

    const __half* gA  = ph_buf + (size_t)(bm + r0) * KLT + kbase + cc * 8;
    const __half* gB0 = w2th_buf + (size_t)r0 * KLT + kbase + cc * 8;
    const __half* gB1 = gB0 + 64 * KLT;

    const int mw = (wid & 1) * 32;
    const int nw = (wid >> 1) * 32;
    const int rowA_l = mw + (lane & 15);
    const int rowB_l = (lane & 7) | ((lane >> 1) & 8);
    u32 aoff[2], boff[2];
    #pragma unroll
    for (int kk = 0; kk < 2; kk++) {
        int chA = kk * 2 + (lane >> 4);
        int chB = kk * 2 + ((lane >> 3) & 1);
        aoff[kk] = (u32)(rowA_l * 64 + ((chA ^ ((rowA_l >> 1) & 3)) << 4));
        boff[kk] = (u32)(rowB_l * 64 + ((chB ^ ((rowB_l >> 1) & 3)) << 4)) + (u32)(nw * 64) + 4096u;
    }

    float acc[2][4][4];
    #pragma unroll
    for (int i = 0; i < 2; i++)
        #pragma unroll
        for (int j = 0; j < 4; j++)
            #pragma unroll
            for (int e = 0; e < 4; e++) acc[i][j][e] = 0.0f;

    const int NCH = 32;  // K = 1024 per CTA

    #pragma unroll
    for (int c0 = 0; c0 < NST2 - 1; c0++) {
        const u32 base = sb + c0 * STG2;
        const int o = c0 * KC;
        CPA(base + so, gA + o);
        CPA(base + 4096u + so,        gB0 + o);
        CPA(base + 4096u + so + 4096, gB1 + o);
        CP_COMMIT();
    }

    for (int c = 0; c < NCH; c++) {
        CP_WAIT3();
        __syncthreads();

        if (c + NST2 - 1 < NCH) {
            const u32 base = sb + (u32)((c + NST2 - 1) % NST2) * STG2;
            const int o = (c + NST2 - 1) * KC;
            CPA(base + so, gA + o);
            CPA(base + 4096u + so,        gB0 + o);
            CPA(base + 4096u + so + 4096, gB1 + o);
        }
        CP_COMMIT();

        const u32 tb = sb + (u32)(c % NST2) * STG2;
        #pragma unroll
        for (int kk = 0; kk < 2; kk++) {
            u32 Af[2][4], Bv[8];
            #pragma unroll
            for (int f = 0; f < 2; f++)
                LDSM_X4(Af[f][0], Af[f][1], Af[f][2], Af[f][3],
                        tb + aoff[kk] + (u32)(f * 1024));
            #pragma unroll
            for (int gi = 0; gi < 2; gi++)
                LDSM_X4(Bv[4 * gi], Bv[4 * gi + 1], Bv[4 * gi + 2], Bv[4 * gi + 3],
                        tb + boff[kk] + (u32)(gi * 1024));
            #pragma unroll
            for (int f = 0; f < 2; f++)
                #pragma unroll
                for (int n = 0; n < 4; n++)
                    MMA16816(acc[f][n], Af[f], Bv[2 * n], Bv[2 * n + 1]);
        }
    }

    float* outp = part_buf + (size_t)z * (BATCH * LDIM);
    #pragma unroll
    for (int f = 0; f < 2; f++) {
        #pragma unroll
        for (int half = 0; half < 2; half++) {
            const int row_l = mw + f * 16 + (lane >> 2) + half * 8;
            #pragma unroll
            for (int n = 0; n < 4; n++) {
                const int col_l = nw + n * 8 + 2 * (lane & 3);
                float* o = outp + (size_t)(bm + row_l) * LDIM + col_l;
                *(float2*)o = make_float2(acc[f][n][2 * half + 0],
                                          acc[f][n][2 * half + 1]);
            }
        }
    }
}

// ---------------- fused preprocessing: convx | transw | w2 ----------------
__global__ __launch_bounds__(256)
void prep_kernel(const float* __restrict__ x, const float* __restrict__ W,
                 const float* __restrict__ leaf_weight, const float* __restrict__ gates) {
    const int blk = blockIdx.x;
    const int tid = threadIdx.x;

    if (blk < 1024) {
        #pragma unroll
        for (int r = 0; r < 2; r++) {
            const int i = blk * 512 + r * 256 + tid;
            float4 v = ((const float4*)x)[i];
            ((__half2*)xh_buf)[2 * i]     = __floats2half2_rn(v.x, v.y);
            ((__half2*)xh_buf)[2 * i + 1] = __floats2half2_rn(v.z, v.w);
        }
    } else if (blk < 2048) {
        const int bb = blk - 1024;
        const int n = bb >> 4;
        const int kb = bb & 15;
        if (n == 63) {
            #pragma unroll
            for (int i = 0; i < 8; i++) {
                int idx = i * 256 + tid;
                int r = idx >> 5, kk = idx & 31;
                wth_buf[(size_t)(4032 + r) * DIN + kb * 32 + kk] = __float2half_rn(0.0f);
            }
            return;
        }
        __shared__ float ts[32][65];
        const int t = tid & 63;
        const int kk0 = tid >> 6;
        #pragma unroll
        for (int i = 0; i < 8; i++) {
            int kk = kk0 + 4 * i;
            ts[kk][t] = W[(size_t)n * (DIN * NTREES) + (size_t)(kb * 32 + kk) * NTREES + t];
        }
        __syncthreads();
        const int kk = tid & 31;
        const int t0 = tid >> 5;
        #pragma unroll
        for (int i = 0; i < 8; i++) {
            int tt = t0 + 8 * i;
            wth_buf[(size_t)(n * 64 + tt) * DIN + kb * 32 + kk] = __float2half_rn(ts[kk][tt]);
        }
    } else {
        const int warp = tid >> 5;
        const int lane = tid & 31;
        const int idx = (blk - 2048) * 8 + warp;
        const int l = idx >> 7;
        const int d = idx & 127;

        const size_t base = ((size_t)l * LDIM + d) * NTREES;
        const float2 gv = ((const float2*)(gates + base))[lane];

        float mx = fmaxf(gv.x, gv.y);
        #pragma unroll
        for (int s = 16; s > 0; s >>= 1) mx = fmaxf(mx, __shfl_xor_sync(0xFFFFFFFFu, mx, s));

        const float e0 = expf(gv.x - mx);
        const float e1 = expf(gv.y - mx);
        float sm = e0 + e1;
        #pragma unroll
        for (int s = 16; s > 0; s >>= 1) sm += __shfl_xor_sync(0xFFFFFFFFu, sm, s);
        const float inv = 1.0f / sm;

        const float2 lwv = ((const float2*)(leaf_weight + base))[lane];
        __half2 r = __floats2half2_rn(lwv.x * e0 * inv, lwv.y * e1 * inv);
        ((__half2*)(w2th_buf + (size_t)d * KLT + l * 64))[lane] = r;
    }
}

// ---------------- tree propagation, half2: thread = (b, tree-pair, z) ----------------
__global__ __launch_bounds__(256)
void prop_kernel(int b_off) {
    const int id = blockIdx.x * blockDim.x + threadIdx.x;
    const int tp = id & 31;             // tree pair (t = 2*tp, 2*tp+1)
    const int z  = (id >> 5) & 7;       // level-3 subtree
    const int b  = b_off + (id >> 8);

    const __half2* g2 = (const __half2*)(g_buf + (size_t)b * GCOLS) + tp;

    float2 f0  = __half22float2(g2[0]);
    float2 f1  = __half22float2(g2[(size_t)(1 + (z >> 2)) * 32]);
    float2 f2  = __half22float2(g2[(size_t)(3 + (z >> 1)) * 32]);
    float2 f3  = __half22float2(g2[(size_t)(7 + z) * 32]);
    float2 f4a = __half22float2(g2[(size_t)(15 + 2 * z) * 32]);
    float2 f4b = __half22float2(g2[(size_t)(16 + 2 * z) * 32]);
    float2 f5[4];
    #pragma unroll
    for (int j = 0; j < 4; j++)
        f5[j] = __half22float2(g2[(size_t)(31 + 4 * z + j) * 32]);

    const int b0 = (z >> 2) & 1, b1 = (z >> 1) & 1, b2 = z & 1;

    float qx[8], qy[8];
    {
        float pre = (b0 ? (1.0f - f0.x) : f0.x)
                  * (b1 ? (1.0f - f1.x) : f1.x)
                  * (b2 ? (1.0f - f2.x) : f2.x);
        float q30 = pre * f3.x, q31 = pre * (1.0f - f3.x);
        float q4[4] = { q30 * f4a.x, q30 * (1.0f - f4a.x),
                        q31 * f4b.x, q31 * (1.0f - f4b.x) };
        #pragma unroll
        for (int m = 0; m < 4; m++) {
            qx[2 * m]     = q4[m] * f5[m].x;
            qx[2 * m + 1] = q4[m] * (1.0f - f5[m].x);
        }
    }
    {
        float pre = (b0 ? (1.0f - f0.y) : f0.y)
                  * (b1 ? (1.0f - f1.y) : f1.y)
                  * (b2 ? (1.0f - f2.y) : f2.y);
        float q30 = pre * f3.y, q31 = pre * (1.0f - f3.y);
        float q4[4] = { q30 * f4a.y, q30 * (1.0f - f4a.y),
                        q31 * f4b.y, q31 * (1.0f - f4b.y) };
        #pragma unroll
        for (int m = 0; m < 4; m++) {
            qy[2 * m]     = q4[m] * f5[m].y;
            qy[2 * m + 1] = q4[m] * (1.0f - f5[m].y);
        }
    }

    __half2* oph = (__half2*)(ph_buf + (size_t)b * KLT + (size_t)z * 8 * 64) + tp;
    #pragma unroll
    for (int j = 0; j < 8; j++)
        oph[(size_t)j * 32] = __floats2half2_rn(qx[j], qy[j]);
}

// ---------------- deterministic split-K reduce (float4) ----------------
__global__ __launch_bounds__(256)
void reduce_kernel(float* __restrict__ out) {
    const int i = blockIdx.x * blockDim.x + threadIdx.x;   // float4 index
    const size_t S4 = (size_t)BATCH * LDIM / 4;
    float4 a0 = ((const float4*)part_buf)[i];
    float4 a1 = ((const float4*)part_buf)[S4 + i];
    float4 a2 = ((const float4*)part_buf)[2 * S4 + i];
    float4 a3 = ((const float4*)part_buf)[3 * S4 + i];
    float4 r;
    r.x = a0.x + a1.x + a2.x + a3.x;
    r.y = a0.y + a1.y + a2.y + a3.y;
    r.z = a0.z + a1.z + a2.z + a3.z;
    r.w = a0.w + a1.w + a2.w + a3.w;
    ((float4*)out)[i] = r;
}

// ============================================================================
extern "C" void kernel_launch(void* const* d_in, const int* in_sizes, int n_in,
                              void* d_out, int out_size) {
    (void)in_sizes; (void)n_in; (void)out_size;
    const float* x     = (const float*)d_in[0];
    const float* W     = (const float*)d_in[1];
    const float* bias  = (const float*)d_in[2];
    const float* lw    = (const float*)d_in[3];
    const float* gates = (const float*)d_in[4];
    float* out = (float*)d_out;

    // created once, before any capture (first call is the uncaptured
    // correctness run); reused on the capture call. No device memory.
    static cudaStream_t s1 = nullptr;
    static cudaEvent_t ev1 = nullptr, ev2 = nullptr;
    if (s1 == nullptr) {
        cudaStreamCreateWithFlags(&s1, cudaStreamNonBlocking);
        cudaEventCreateWithFlags(&ev1, cudaEventDisableTiming);
        cudaEventCreateWithFlags(&ev2, cudaEventDisableTiming);
    }

    cudaFuncSetAttribute((const void*)hmma1_kernel,
                         cudaFuncAttributeMaxDynamicSharedMemorySize, SMEM_G1);
    cudaFuncSetAttribute((const void*)hmma2_kernel,
                         cudaFuncAttributeMaxDynamicSharedMemorySize, SMEM_G2);

    const int HB1 = (BATCH / 128) / 2;     // 16 bm tiles per half (GEMM1)
    const int HB2 = (BATCH / 64) / 2;      // 32 bm tiles per half (GEMM2)
    const int HPROP = (BATCH / 2 * 32 * 8) / 256;  // 2048 blocks per half

    // s0 (legacy default stream): prep -> h1a -> [ev1] -> h1b -> prop_b -> h2b
    prep_kernel<<<3072, 256>>>(x, W, lw, gates);

    hmma1_kernel<<<dim3(GCOLS / 128, HB1), 256, SMEM_G1>>>(bias, 0);
    cudaEventRecord(ev1, 0);

    hmma1_kernel<<<dim3(GCOLS / 128, HB1), 256, SMEM_G1>>>(bias, HB1);

    // s1: wait h1a -> prop_a -> h2a -> [ev2]
    cudaStreamWaitEvent(s1, ev1, 0);
    prop_kernel<<<HPROP, 256, 0, s1>>>(0);
    hmma2_kernel<<<dim3(HB2, SPLITK2), 256, SMEM_G2, s1>>>(0);
    cudaEventRecord(ev2, s1);

    // s0 continues: prop_b -> h2b -> join ev2 -> reduce
    prop_kernel<<<HPROP, 256>>>(BATCH / 2);
    hmma2_kernel<<<dim3(HB2, SPLITK2), 256, SMEM_G2>>>(HB2);

    cudaStreamWaitEvent(0, ev2, 0);
    reduce_kernel<<<(BATCH * LDIM / 4) / 256, 256>>>(out);
}

// round 17
// speedup vs baseline: 1.0241x; 1.0241x over previous
#include <cuda_runtime.h>
#include <cuda_fp16.h>
#include <cstdint>

typedef unsigned long long u64;
typedef unsigned int u32;

#define BATCH   4096
#define DIN     512
#define NTREES  64
#define NCOLSV  4032        // valid gate columns
#define GCOLS   4096        // padded gate columns
#define KLT     4096
#define LDIM    128
#define SPLITK2 4

// ---------------- scratch (device globals: allocation-free) ----------------
__device__ __half g_buf[(size_t)BATCH * GCOLS];     // sigmoid gates [b][col] fp16
__device__ __half xh_buf[(size_t)BATCH * DIN];      // x fp16
__device__ __half wth_buf[(size_t)GCOLS * DIN];     // W transposed [col][k] fp16
__device__ __half ph_buf[(size_t)BATCH * KLT];      // leaf probs fp16
__device__ __half w2th_buf[(size_t)LDIM * KLT];     // leaf_w*softmax transposed fp16
__device__ float  part_buf[SPLITK2 * (size_t)BATCH * LDIM];

// ---------------- helpers ----------------
__device__ __forceinline__ u32 smem_u32(const void* p) {
    u32 a;
    asm("{ .reg .u64 t; cvta.to.shared.u64 t, %1; cvt.u32.u64 %0, t; }" : "=r"(a) : "l"(p));
    return a;
}
// fast sigmoid: guaranteed MUFU path independent of compile flags
__device__ __forceinline__ float sigf(float z) {
    return __fdividef(1.0f, 1.0f + __expf(-z));
}

#define LDSM_X4(r0, r1, r2, r3, addr) \
    asm volatile("ldmatrix.sync.aligned.m8n8.x4.shared.b16 {%0,%1,%2,%3}, [%4];" \
                 : "=r"(r0), "=r"(r1), "=r"(r2), "=r"(r3) : "r"(addr))

#define MMA16816(d, a, b0, b1) \
    asm volatile("mma.sync.aligned.m16n8k16.row.col.f32.f16.f16.f32 " \
                 "{%0,%1,%2,%3}, {%4,%5,%6,%7}, {%8,%9}, {%0,%1,%2,%3};" \
                 : "+f"((d)[0]), "+f"((d)[1]), "+f"((d)[2]), "+f"((d)[3]) \
                 : "r"((a)[0]), "r"((a)[1]), "r"((a)[2]), "r"((a)[3]), \
                   "r"(b0), "r"(b1))

#define CPA(dst, src) \
    asm volatile("cp.async.cg.shared.global [%0], [%1], 16;" :: "r"(dst), "l"(src))
#define CP_COMMIT() asm volatile("cp.async.commit_group;" ::: "memory")
#define CP_WAIT3()  asm volatile("cp.async.wait_group 3;" ::: "memory")

// ============================================================================
// GEMM1: g = sigmoid(x @ wt^T + bias) -> fp16.  grid (32, 32), 256 threads.
// C[128,128] CTA tile, 8 warps of 64x32, K-chunks of 32, 5-stage cp.async.
// Swizzle: 16B chunk c' = c ^ ((row>>1)&3); row stride 64B.   (R12 config)
// ============================================================================
#define KC 32
#define NSTAGE 5
#define T_BH   8192u
#define STG_B  16384u
#define OFF_BIAS (NSTAGE * STG_B)
#define SMEM_G1 (OFF_BIAS + 512)

__global__ __launch_bounds__(256, 2)
void hmma1_kernel(const float* __restrict__ bias) {
    extern __shared__ char smem[];
    const u32 sb = smem_u32(smem);
    const int tid  = threadIdx.x;
    const int wid  = tid >> 5;
    const int lane = tid & 31;

    const int bn = blockIdx.x * 128;
    const int bm = blockIdx.y * 128;

    if (tid < 128) {
        int col = bn + tid;
        ((float*)(smem + OFF_BIAS))[tid] = (col < NCOLSV) ? bias[col] : 0.0f;
    }

    const int r0 = tid >> 2;
    const int cc = tid & 3;
    const u32 so = (u32)(r0 * 64 + ((cc ^ ((r0 >> 1) & 3)) << 4));

    const __half* gA0 = xh_buf + (size_t)(bm + r0) * DIN + cc * 8;
    const __half* gA1 = gA0 + 64 * DIN;
    const __half* gB0 = wth_buf + (size_t)(bn + r0) * DIN + cc * 8;
    const __half* gB1 = gB0 + 64 * DIN;

    const int mw = (wid & 1) * 64;
    const int nw = (wid >> 1) * 32;
    const int rowA_l = mw + (lane & 15);
    const int rowB_l = (lane & 7) | ((lane >> 1) & 8);
    u32 aoff[2], boff[2];
    #pragma unroll
    for (int kk = 0; kk < 2; kk++) {
        int chA = kk * 2 + (lane >> 4);
        int chB = kk * 2 + ((lane >> 3) & 1);
        aoff[kk] = (u32)(rowA_l * 64 + ((chA ^ ((rowA_l >> 1) & 3)) << 4));
        boff[kk] = (u32)(rowB_l * 64 + ((chB ^ ((rowB_l >> 1) & 3)) << 4)) + (u32)(nw * 64);
    }

    float acc[4][4][4];
    #pragma unroll
    for (int i = 0; i < 4; i++)
        #pragma unroll
        for (int j = 0; j < 4; j++)
            #pragma unroll
            for (int e = 0; e < 4; e++) acc[i][j][e] = 0.0f;

    const int NCH = 16;

    #pragma unroll
    for (int c0 = 0; c0 < NSTAGE - 1; c0++) {
        const u32 base = sb + c0 * STG_B;
        const int o = c0 * KC;
        CPA(base + so,        gA0 + o);
        CPA(base + so + 4096, gA1 + o);
        CPA(base + T_BH + so,        gB0 + o);
        CPA(base + T_BH + so + 4096, gB1 + o);
        CP_COMMIT();
    }

    int sc = NSTAGE - 1;
    for (int c = 0; c < NCH; c++) {
        CP_WAIT3();
        __syncthreads();

        if (c + NSTAGE - 1 < NCH) {
            const u32 base = sb + sc * STG_B;
            const int o = (c + NSTAGE - 1) * KC;
            CPA(base + so,        gA0 + o);
            CPA(base + so + 4096, gA1 + o);
            CPA(base + T_BH + so,        gB0 + o);
            CPA(base + T_BH + so + 4096, gB1 + o);
        }
        CP_COMMIT();
        sc = (sc == NSTAGE - 1) ? 0 : sc + 1;

        const u32 tb = sb + (u32)(c % NSTAGE) * STG_B;
        #pragma unroll
        for (int kk = 0; kk < 2; kk++) {
            u32 Af[4][4], Bv[8];
            #pragma unroll
            for (int f = 0; f < 4; f++)
                LDSM_X4(Af[f][0], Af[f][1], Af[f][2], Af[f][3],
                        tb + aoff[kk] + (u32)(f * 1024));
            #pragma unroll
            for (int gi = 0; gi < 2; gi++)
                LDSM_X4(Bv[4 * gi], Bv[4 * gi + 1], Bv[4 * gi + 2], Bv[4 * gi + 3],
                        tb + T_BH + boff[kk] + (u32)(gi * 1024));
            #pragma unroll
            for (int f = 0; f < 4; f++)
                #pragma unroll
                for (int n = 0; n < 4; n++)
                    MMA16816(acc[f][n], Af[f], Bv[2 * n], Bv[2 * n + 1]);
        }
    }

    const float* bias_s = (const float*)(smem + OFF_BIAS);
    #pragma unroll
    for (int f = 0; f < 4; f++) {
        #pragma unroll
        for (int half = 0; half < 2; half++) {
            const int row_l = mw + f * 16 + (lane >> 2) + half * 8;
            #pragma unroll
            for (int n = 0; n < 4; n++) {
                const int col_l = nw + n * 8 + 2 * (lane & 3);
                float v0 = sigf(acc[f][n][2 * half + 0] + bias_s[col_l]);
                float v1 = sigf(acc[f][n][2 * half + 1] + bias_s[col_l + 1]);
                __half2* o = (__half2*)(g_buf + (size_t)(bm + row_l) * GCOLS + bn + col_l);
                *o = __floats2half2_rn(v0, v1);
            }
        }
    }
}

// ============================================================================
// GEMM2: part[z] = p @ w2t^T (split-K=4).  grid (64 m-tiles, 4 z) = 256 CTAs.
// C[64,128] CTA tile, 8 warps of 32x32, K=1024 per CTA in 32 chunks of 32,
// 5-stage cp.async.  Stage = A(4KB)+B(8KB) = 12KB.   (R12 config)
// ============================================================================
#define NST2  5
#define STG2  12288u
#define SMEM_G2 (NST2 * STG2)

__global__ __launch_bounds__(256, 2)
void hmma2_kernel() {
    extern __shared__ char smem[];
    const u32 sb = smem_u32(smem);
    const int tid  = threadIdx.x;
    const int wid  = tid >> 5;
    const int lane = tid & 31;

    const int bm = blockIdx.x * 64;
    const int z  = blockIdx.y;
    const long kbase = (long)z * 1024;

    const int r0 = tid >> 2;            // 0..63
    const int cc = tid & 3;
    const u32 so = (u32)(r0 * 64 + ((cc ^ ((r0 >> 1) & 3)) << 4));

    const __half* gA  = ph_buf + (size_t)(bm + r0) * KLT + kbase + cc * 8;
    const __half* gB0 = w2th_buf + (size_t)r0 * KLT + kbase + cc * 8;
    const __half* gB1 = gB0 + 64 * KLT;

    const int mw = (wid & 1) * 32;
    const int nw = (wid >> 1) * 32;
    const int rowA_l = mw + (lane & 15);
    const int rowB_l = (lane & 7) | ((lane >> 1) & 8);
    u32 aoff[2], boff[2];
    #pragma unroll
    for (int kk = 0; kk < 2; kk++) {
        int chA = kk * 2 + (lane >> 4);
        int chB = kk * 2 + ((lane >> 3) & 1);
        aoff[kk] = (u32)(rowA_l * 64 + ((chA ^ ((rowA_l >> 1) & 3)) << 4));
        boff[kk] = (u32)(rowB_l * 64 + ((chB ^ ((rowB_l >> 1) & 3)) << 4)) + (u32)(nw * 64) + 4096u;
    }

    float acc[2][4][4];
    #pragma unroll
    for (int i = 0; i < 2; i++)
        #pragma unroll
        for (int j = 0; j < 4; j++)
            #pragma unroll
            for (int e = 0; e < 4; e++) acc[i][j][e] = 0.0f;

    const int NCH = 32;  // K = 1024 per CTA

    #pragma unroll
    for (int c0 = 0; c0 < NST2 - 1; c0++) {
        const u32 base = sb + c0 * STG2;
        const int o = c0 * KC;
        CPA(base + so, gA + o);
        CPA(base + 4096u + so,        gB0 + o);
        CPA(base + 4096u + so + 4096, gB1 + o);
        CP_COMMIT();
    }

    for (int c = 0; c < NCH; c++) {
        CP_WAIT3();
        __syncthreads();

        if (c + NST2 - 1 < NCH) {
            const u32 base = sb + (u32)((c + NST2 - 1) % NST2) * STG2;
            const int o = (c + NST2 - 1) * KC;
            CPA(base + so, gA + o);
            CPA(base + 4096u + so,        gB0 + o);
            CPA(base + 4096u + so + 4096, gB1 + o);
        }
        CP_COMMIT();

        const u32 tb = sb + (u32)(c % NST2) * STG2;
        #pragma unroll
        for (int kk = 0; kk < 2; kk++) {
            u32 Af[2][4], Bv[8];
            #pragma unroll
            for (int f = 0; f < 2; f++)
                LDSM_X4(Af[f][0], Af[f][1], Af[f][2], Af[f][3],
                        tb + aoff[kk] + (u32)(f * 1024));
            #pragma unroll
            for (int gi = 0; gi < 2; gi++)
                LDSM_X4(Bv[4 * gi], Bv[4 * gi + 1], Bv[4 * gi + 2], Bv[4 * gi + 3],
                        tb + boff[kk] + (u32)(gi * 1024));
            #pragma unroll
            for (int f = 0; f < 2; f++)
                #pragma unroll
                for (int n = 0; n < 4; n++)
                    MMA16816(acc[f][n], Af[f], Bv[2 * n], Bv[2 * n + 1]);
        }
    }

    float* outp = part_buf + (size_t)z * (BATCH * LDIM);
    #pragma unroll
    for (int f = 0; f < 2; f++) {
        #pragma unroll
        for (int half = 0; half < 2; half++) {
            const int row_l = mw + f * 16 + (lane >> 2) + half * 8;
            #pragma unroll
            for (int n = 0; n < 4; n++) {
                const int col_l = nw + n * 8 + 2 * (lane & 3);
                float* o = outp + (size_t)(bm + row_l) * LDIM + col_l;
                *(float2*)o = make_float2(acc[f][n][2 * half + 0],
                                          acc[f][n][2 * half + 1]);
            }
        }
    }
}

// ---------------- fused preprocessing: convx | transw | w2 ----------------
// grid = 3072 blocks x 256 threads:
//   [0, 1024)    : x -> fp16              (two float4 per thread)
//   [1024, 2048) : W transpose -> fp16    (n = blk/16, kb = blk%16)
//   [2048, 3072) : softmax*leaf_w -> fp16 (8 warps, one (l,d) each)
__global__ __launch_bounds__(256)
void prep_kernel(const float* __restrict__ x, const float* __restrict__ W,
                 const float* __restrict__ leaf_weight, const float* __restrict__ gates) {
    const int blk = blockIdx.x;
    const int tid = threadIdx.x;

    if (blk < 1024) {
        #pragma unroll
        for (int r = 0; r < 2; r++) {
            const int i = blk * 512 + r * 256 + tid;
            float4 v = ((const float4*)x)[i];
            ((__half2*)xh_buf)[2 * i]     = __floats2half2_rn(v.x, v.y);
            ((__half2*)xh_buf)[2 * i + 1] = __floats2half2_rn(v.z, v.w);
        }
    } else if (blk < 2048) {
        const int bb = blk - 1024;
        const int n = bb >> 4;
        const int kb = bb & 15;
        if (n == 63) {
            #pragma unroll
            for (int i = 0; i < 8; i++) {
                int idx = i * 256 + tid;
                int r = idx >> 5, kk = idx & 31;
                wth_buf[(size_t)(4032 + r) * DIN + kb * 32 + kk] = __float2half_rn(0.0f);
            }
            return;
        }
        __shared__ float ts[32][65];
        const int t = tid & 63;
        const int kk0 = tid >> 6;
        #pragma unroll
        for (int i = 0; i < 8; i++) {
            int kk = kk0 + 4 * i;
            ts[kk][t] = W[(size_t)n * (DIN * NTREES) + (size_t)(kb * 32 + kk) * NTREES + t];
        }
        __syncthreads();
        const int kk = tid & 31;
        const int t0 = tid >> 5;
        #pragma unroll
        for (int i = 0; i < 8; i++) {
            int tt = t0 + 8 * i;
            wth_buf[(size_t)(n * 64 + tt) * DIN + kb * 32 + kk] = __float2half_rn(ts[kk][tt]);
        }
    } else {
        const int warp = tid >> 5;
        const int lane = tid & 31;
        const int idx = (blk - 2048) * 8 + warp;
        const int l = idx >> 7;
        const int d = idx & 127;

        const size_t base = ((size_t)l * LDIM + d) * NTREES;
        const float2 gv = ((const float2*)(gates + base))[lane];

        float mx = fmaxf(gv.x, gv.y);
        #pragma unroll
        for (int s = 16; s > 0; s >>= 1) mx = fmaxf(mx, __shfl_xor_sync(0xFFFFFFFFu, mx, s));

        const float e0 = expf(gv.x - mx);
        const float e1 = expf(gv.y - mx);
        float sm = e0 + e1;
        #pragma unroll
        for (int s = 16; s > 0; s >>= 1) sm += __shfl_xor_sync(0xFFFFFFFFu, sm, s);
        const float inv = 1.0f / sm;

        const float2 lwv = ((const float2*)(leaf_weight + base))[lane];
        __half2 r = __floats2half2_rn(lwv.x * e0 * inv, lwv.y * e1 * inv);
        ((__half2*)(w2th_buf + (size_t)d * KLT + l * 64))[lane] = r;
    }
}

// ---------------- tree propagation, half2, z-pair shared loads ----------------
// thread = (b, tree-pair tp, zz); handles subtrees z = 2*zz and 2*zz+1,
// sharing the level-0/1/2 gate loads (identical offsets for the pair).
__global__ __launch_bounds__(256)
void prop_kernel() {
    const int id = blockIdx.x * blockDim.x + threadIdx.x;  // 0 .. 512K-1
    const int tp = id & 31;             // tree pair (t = 2*tp, 2*tp+1)
    const int zz = (id >> 5) & 3;       // subtree pair (z = 2*zz, 2*zz+1)
    const int b  = id >> 7;

    const __half2* g2 = (const __half2*)(g_buf + (size_t)b * GCOLS) + tp;

    // shared across the z-pair: levels 0..2
    const float2 f0 = __half22float2(g2[0]);
    const float2 f1 = __half22float2(g2[(size_t)(1 + (zz >> 1)) * 32]);
    const float2 f2 = __half22float2(g2[(size_t)(3 + zz) * 32]);

    const int b0 = (zz >> 1) & 1, b1 = zz & 1;
    // pre01 = (t0*t1); per-z pre = pre01 * t2   (same association as ((t0*t1)*t2))
    const float pre01x = (b0 ? (1.0f - f0.x) : f0.x) * (b1 ? (1.0f - f1.x) : f1.x);
    const float pre01y = (b0 ? (1.0f - f0.y) : f0.y) * (b1 ? (1.0f - f1.y) : f1.y);

    #pragma unroll
    for (int b2 = 0; b2 < 2; b2++) {
        const int z = 2 * zz + b2;

        const float2 f3  = __half22float2(g2[(size_t)(7 + z) * 32]);
        const float2 f4a = __half22float2(g2[(size_t)(15 + 2 * z) * 32]);
        const float2 f4b = __half22float2(g2[(size_t)(16 + 2 * z) * 32]);
        float2 f5[4];
        #pragma unroll
        for (int j = 0; j < 4; j++)
            f5[j] = __half22float2(g2[(size_t)(31 + 4 * z + j) * 32]);

        float qx[8], qy[8];
        {
            const float pre = pre01x * (b2 ? (1.0f - f2.x) : f2.x);
            const float q30 = pre * f3.x, q31 = pre * (1.0f - f3.x);
            const float q4[4] = { q30 * f4a.x, q30 * (1.0f - f4a.x),
                                  q31 * f4b.x, q31 * (1.0f - f4b.x) };
            #pragma unroll
            for (int m = 0; m < 4; m++) {
                qx[2 * m]     = q4[m] * f5[m].x;
                qx[2 * m + 1] = q4[m] * (1.0f - f5[m].x);
            }
        }
        {
            const float pre = pre01y * (b2 ? (1.0f - f2.y) : f2.y);
            const float q30 = pre * f3.y, q31 = pre * (1.0f - f3.y);
            const float q4[4] = { q30 * f4a.y, q30 * (1.0f - f4a.y),
                                  q31 * f4b.y, q31 * (1.0f - f4b.y) };
            #pragma unroll
            for (int m = 0; m < 4; m++) {
                qy[2 * m]     = q4[m] * f5[m].y;
                qy[2 * m + 1] = q4[m] * (1.0f - f5[m].y);
            }
        }

        __half2* oph = (__half2*)(ph_buf + (size_t)b * KLT + (size_t)z * 8 * 64) + tp;
        #pragma unroll
        for (int j = 0; j < 8; j++)
            oph[(size_t)j * 32] = __floats2half2_rn(qx[j], qy[j]);
    }
}

// ---------------- deterministic split-K reduce (float4) ----------------
__global__ __launch_bounds__(256)
void reduce_kernel(float* __restrict__ out) {
    const int i = blockIdx.x * blockDim.x + threadIdx.x;   // float4 index
    const size_t S4 = (size_t)BATCH * LDIM / 4;
    float4 a0 = ((const float4*)part_buf)[i];
    float4 a1 = ((const float4*)part_buf)[S4 + i];
    float4 a2 = ((const float4*)part_buf)[2 * S4 + i];
    float4 a3 = ((const float4*)part_buf)[3 * S4 + i];
    float4 r;
    r.x = a0.x + a1.x + a2.x + a3.x;
    r.y = a0.y + a1.y + a2.y + a3.y;
    r.z = a0.z + a1.z + a2.z + a3.z;
    r.w = a0.w + a1.w + a2.w + a3.w;
    ((float4*)out)[i] = r;
}

// ============================================================================
extern "C" void kernel_launch(void* const* d_in, const int* in_sizes, int n_in,
                              void* d_out, int out_size) {
    (void)in_sizes; (void)n_in; (void)out_size;
    const float* x     = (const float*)d_in[0];
    const float* W     = (const float*)d_in[1];
    const float* bias  = (const float*)d_in[2];
    const float* lw    = (const float*)d_in[3];
    const float* gates = (const float*)d_in[4];
    float* out = (float*)d_out;

    cudaFuncSetAttribute((const void*)hmma1_kernel,
                         cudaFuncAttributeMaxDynamicSharedMemorySize, SMEM_G1);
    cudaFuncSetAttribute((const void*)hmma2_kernel,
                         cudaFuncAttributeMaxDynamicSharedMemorySize, SMEM_G2);

    prep_kernel<<<3072, 256>>>(x, W, lw, gates);

    hmma1_kernel<<<dim3(GCOLS / 128, BATCH / 128), 256, SMEM_G1>>>(bias);

    prop_kernel<<<(BATCH * 32 * 4) / 256, 256>>>();

    hmma2_kernel<<<dim3(BATCH / 64, SPLITK2), 256, SMEM_G2>>>();

    reduce_kernel<<<(BATCH * LDIM / 4) / 256, 256>>>(out);
}